// round 4
// baseline (speedup 1.0000x reference)
#include <cuda_runtime.h>
#include <cuda_bf16.h>

#define NKC 5000
#define BB  512
#define TT  100

__device__ float g_c4[NKC];   // sigmoid(logits[:,4]) — initial/default state

__device__ __forceinline__ float sigmoidf(float x) {
    return 1.0f / (1.0f + __expf(-x));
}

// ---- kernel A: tiny table build ----
__global__ void tbl_kernel(const float* __restrict__ logits) {
    int k = blockIdx.x * blockDim.x + threadIdx.x;
    if (k < NKC)
        g_c4[k] = sigmoidf(logits[k * 5 + 4]);
}

// ---- kernel B: broadcast default state to all 512 output rows (pure BW) ----
__global__ __launch_bounds__(256)
void bcast_kernel(float* __restrict__ out) {
    const int b = blockIdx.x;
    const float4* __restrict__ src = (const float4*)g_c4;
    float4* __restrict__ dst = (float4*)(out + (size_t)BB * TT + (size_t)b * NKC);
    #pragma unroll
    for (int i = threadIdx.x; i < NKC / 4; i += 256)
        dst[i] = src[i];
}

// ---- kernel C: recurrence resolve + probs + sparse state patch ----
__global__ __launch_bounds__(128)
void solve_kernel(const int* __restrict__ prev_kc,
                  const int* __restrict__ curr_kc,
                  const int* __restrict__ prev_corr,
                  const float* __restrict__ logits,
                  float* __restrict__ out)
{
    __shared__ int   sPK[128];     // padded to 128 for int4 scan
    __shared__ int   sPW[TT];
    __shared__ float sVal[TT];
    __shared__ int   sMaxD;

    const int b   = blockIdx.x;
    const int tid = threadIdx.x;

    // ---- load + inline sigmoid constants ----
    int   pk = -1, ck = -1;
    float A = 0.f, Bc = 0.f, P0 = 0.f, E = 0.f, F = 0.f, G = 0.f;
    float initSkill = 0.f, initCs = 0.f;

    sPK[tid] = -9;                 // padding sentinel (never matches a kc)
    if (tid == 0) sMaxD = 0;

    if (tid < TT) {
        ck = curr_kc[b * TT + tid];
        pk = prev_kc[b * TT + tid];
        const int c = prev_corr[b * TT + tid];
        const float c2 = sigmoidf(logits[ck * 5 + 2]);
        const float c3 = sigmoidf(logits[ck * 5 + 3]);
        G = c2;
        F = c3 - c2;
        initCs = sigmoidf(logits[ck * 5 + 4]);
        if (tid >= 1) {
            sPK[tid] = pk;
            const float p0 = sigmoidf(logits[pk * 5 + 0]);
            const float p1 = sigmoidf(logits[pk * 5 + 1]);
            const float p2 = sigmoidf(logits[pk * 5 + 2]);
            const float p3 = sigmoidf(logits[pk * 5 + 3]);
            A  = c ? p3 : (1.0f - p3);    // p_out[:,1]
            Bc = c ? p2 : (1.0f - p2);    // p_out[:,0]
            P0 = p0;
            E  = 1.0f - p1 - p0;
            initSkill = sigmoidf(logits[pk * 5 + 4]);
        }
    }
    __syncthreads();

    // ---- int4 dependency scan over all 128 (padded) steps ----
    int  pw = -1;          // last s' <  tid writing pk  (skill source)
    int  w  = -1;          // last s' <= tid writing ck  (probs source)
    bool isLast = true;    // no s' > tid writes pk
    if (tid < TT) {
        const int4* sp4 = (const int4*)sPK;
        #pragma unroll 8
        for (int j = 0; j < 32; j++) {
            const int4 v = *(sp4 + j);
            const int s0 = 4 * j;
            if (v.x == pk) { if (s0     < tid) pw = s0;     else if (s0     > tid) isLast = false; }
            if (v.y == pk) { if (s0 + 1 < tid) pw = s0 + 1; else if (s0 + 1 > tid) isLast = false; }
            if (v.z == pk) { if (s0 + 2 < tid) pw = s0 + 2; else if (s0 + 2 > tid) isLast = false; }
            if (v.w == pk) { if (s0 + 3 < tid) pw = s0 + 3; else if (s0 + 3 > tid) isLast = false; }
            if (v.x == ck && s0     <= tid) w = s0;
            if (v.y == ck && s0 + 1 <= tid) w = s0 + 1;
            if (v.z == ck && s0 + 2 <= tid) w = s0 + 2;
            if (v.w == ck && s0 + 3 <= tid) w = s0 + 3;
        }
        sPW[tid] = pw;
    }
    __syncthreads();

    // ---- chain depth via pointer chase (depth is tiny: ~1-4) ----
    int depth = 0;
    if (tid >= 1 && tid < TT) {
        int j = pw;
        while (j >= 0) { j = sPW[j]; depth++; }
        atomicMax(&sMaxD, depth);
    }
    __syncthreads();
    const int maxD = sMaxD;

    // ---- wavefront by depth: one barrier per round ----
    float myVal = 0.f;
    for (int r = 0; r <= maxD; r++) {
        if (tid >= 1 && tid < TT && depth == r) {
            const float skill = (r == 0) ? initSkill : sVal[pw];
            const float num   = A * skill;
            const float den   = fmaf(Bc, -skill, Bc) + num;   // B*(1-skill)+A*skill
            const float filt  = __fdividef(num, den);
            myVal = fmaf(E, filt, P0);
            sVal[tid] = myVal;
        }
        __syncthreads();
    }

    // ---- probs ----
    if (tid < TT) {
        const float cs = (w < 0) ? initCs : sVal[w];
        out[b * TT + tid] = fmaf(F, cs, G);
    }

    // ---- sparse patch of final state (over bcast_kernel's copy) ----
    if (tid >= 1 && tid < TT && isLast)
        out[(size_t)BB * TT + (size_t)b * NKC + pk] = myVal;
}

extern "C" void kernel_launch(void* const* d_in, const int* in_sizes, int n_in,
                              void* d_out, int out_size) {
    const int*   prev_kc   = (const int*)d_in[0];
    const int*   curr_kc   = (const int*)d_in[1];
    const int*   prev_corr = (const int*)d_in[2];
    const float* kc_logits = (const float*)d_in[3];
    float*       out       = (float*)d_out;

    tbl_kernel  <<<(NKC + 255) / 256, 256>>>(kc_logits);
    bcast_kernel<<<BB, 256>>>(out);
    solve_kernel<<<BB, 128>>>(prev_kc, curr_kc, prev_corr, kc_logits, out);
}

// round 5
// speedup vs baseline: 1.1210x; 1.1210x over previous
#include <cuda_runtime.h>
#include <cuda_bf16.h>

#define NKC 5000
#define BB  512
#define TT  100
#define THREADS 256

__device__ float g_c4[NKC];   // sigmoid(logits[:,4]) — initial/default state

__device__ __forceinline__ float sigmoidf(float x) {
    return 1.0f / (1.0f + __expf(-x));
}

// ---- kernel A: tiny table build ----
__global__ void tbl_kernel(const float* __restrict__ logits) {
    int k = blockIdx.x * blockDim.x + threadIdx.x;
    if (k < NKC)
        g_c4[k] = sigmoidf(logits[k * 5 + 4]);
}

// ---- kernel B: fused broadcast-copy + recurrence resolve + probs + patch ----
__global__ __launch_bounds__(THREADS)
void fused_kernel(const int* __restrict__ prev_kc,
                  const int* __restrict__ curr_kc,
                  const int* __restrict__ prev_corr,
                  const float* __restrict__ logits,
                  float* __restrict__ out)
{
    __shared__ int   sPK[128];     // padded to 128 for int4 scan
    __shared__ int   sPW[TT];
    __shared__ float sVal[TT];
    __shared__ int   sMaxD;

    const int b   = blockIdx.x;
    const int tid = threadIdx.x;

    float* __restrict__ orow = out + (size_t)BB * TT + (size_t)b * NKC;

    // ---- phase 0 (split warps): warps 4-7 bulk-copy, warps 0-3 gather ----
    int   pk = -1, ck = -1;
    float A = 0.f, Bc = 0.f, P0 = 0.f, E = 0.f, F = 0.f, G = 0.f;
    float initSkill = 0.f, initCs = 0.f;

    if (tid >= 128) {
        // bulk copy: default state row -> out (g_c4 is L2-resident, 512x reuse)
        const float4* __restrict__ src = (const float4*)g_c4;
        float4*       __restrict__ dst = (float4*)orow;
        #pragma unroll 2
        for (int i = tid - 128; i < NKC / 4; i += 128)
            dst[i] = src[i];
    } else {
        sPK[tid] = -9;             // padding sentinel
        if (tid == 0) sMaxD = 0;
        if (tid < TT) {
            ck = curr_kc[b * TT + tid];
            pk = prev_kc[b * TT + tid];
            const int c = prev_corr[b * TT + tid];
            const float c2 = sigmoidf(logits[ck * 5 + 2]);
            const float c3 = sigmoidf(logits[ck * 5 + 3]);
            G = c2;
            F = c3 - c2;
            initCs = sigmoidf(logits[ck * 5 + 4]);
            if (tid >= 1) {
                sPK[tid] = pk;
                const float p0 = sigmoidf(logits[pk * 5 + 0]);
                const float p1 = sigmoidf(logits[pk * 5 + 1]);
                const float p2 = sigmoidf(logits[pk * 5 + 2]);
                const float p3 = sigmoidf(logits[pk * 5 + 3]);
                A  = c ? p3 : (1.0f - p3);    // p_out[:,1]
                Bc = c ? p2 : (1.0f - p2);    // p_out[:,0]
                P0 = p0;
                E  = 1.0f - p1 - p0;
                initSkill = sigmoidf(logits[pk * 5 + 4]);
            }
        }
    }
    __syncthreads();

    // ---- dependency scan (int4 over padded 128 steps) ----
    int  pw = -1;          // last s' <  tid writing pk  (skill source)
    int  w  = -1;          // last s' <= tid writing ck  (probs source)
    bool isLast = true;    // no s' > tid writes pk
    if (tid < TT) {
        const int4* sp4 = (const int4*)sPK;
        #pragma unroll 8
        for (int j = 0; j < 32; j++) {
            const int4 v = *(sp4 + j);
            const int s0 = 4 * j;
            if (v.x == pk) { if (s0     < tid) pw = s0;     else if (s0     > tid) isLast = false; }
            if (v.y == pk) { if (s0 + 1 < tid) pw = s0 + 1; else if (s0 + 1 > tid) isLast = false; }
            if (v.z == pk) { if (s0 + 2 < tid) pw = s0 + 2; else if (s0 + 2 > tid) isLast = false; }
            if (v.w == pk) { if (s0 + 3 < tid) pw = s0 + 3; else if (s0 + 3 > tid) isLast = false; }
            if (v.x == ck && s0     <= tid) w = s0;
            if (v.y == ck && s0 + 1 <= tid) w = s0 + 1;
            if (v.z == ck && s0 + 2 <= tid) w = s0 + 2;
            if (v.w == ck && s0 + 3 <= tid) w = s0 + 3;
        }
        sPW[tid] = pw;
    }
    __syncthreads();

    // ---- chain depth via pointer chase (depth ~1-4) ----
    int depth = 0;
    if (tid >= 1 && tid < TT) {
        int j = pw;
        while (j >= 0) { j = sPW[j]; depth++; }
        atomicMax(&sMaxD, depth);
    }
    __syncthreads();
    const int maxD = sMaxD;

    // ---- wavefront by depth: one uniform barrier per round ----
    float myVal = 0.f;
    for (int r = 0; r <= maxD; r++) {
        if (tid >= 1 && tid < TT && depth == r) {
            const float skill = (r == 0) ? initSkill : sVal[pw];
            const float num   = A * skill;
            const float den   = fmaf(Bc, -skill, Bc) + num;   // B*(1-skill)+A*skill
            const float filt  = __fdividef(num, den);
            myVal = fmaf(E, filt, P0);
            sVal[tid] = myVal;
        }
        __syncthreads();
    }

    // ---- probs + sparse patch (barriers above order patch after copy) ----
    if (tid < TT) {
        const float cs = (w < 0) ? initCs : sVal[w];
        out[b * TT + tid] = fmaf(F, cs, G);
        if (tid >= 1 && isLast)
            orow[pk] = myVal;
    }
}

extern "C" void kernel_launch(void* const* d_in, const int* in_sizes, int n_in,
                              void* d_out, int out_size) {
    const int*   prev_kc   = (const int*)d_in[0];
    const int*   curr_kc   = (const int*)d_in[1];
    const int*   prev_corr = (const int*)d_in[2];
    const float* kc_logits = (const float*)d_in[3];
    float*       out       = (float*)d_out;

    tbl_kernel  <<<(NKC + 255) / 256, 256>>>(kc_logits);
    fused_kernel<<<BB, THREADS>>>(prev_kc, curr_kc, prev_corr, kc_logits, out);
}

// round 6
// speedup vs baseline: 1.1234x; 1.0021x over previous
#include <cuda_runtime.h>
#include <cuda_bf16.h>

#define NKC 5000
#define BB  512
#define TT  100
#define THREADS 256

__device__ float  g_c4[NKC];   // sigmoid(logits[:,4]) — initial/default state
__device__ float4 g_p4[NKC];   // sigmoid(logits[:,0..3])

__device__ __forceinline__ float sigmoidf(float x) {
    return 1.0f / (1.0f + __expf(-x));
}

// ---- kernel A: tiny table build (only MUFU-heavy work, 5000 wide) ----
__global__ void tbl_kernel(const float* __restrict__ logits) {
    int k = blockIdx.x * blockDim.x + threadIdx.x;
    if (k < NKC) {
        float s0 = sigmoidf(logits[k * 5 + 0]);
        float s1 = sigmoidf(logits[k * 5 + 1]);
        float s2 = sigmoidf(logits[k * 5 + 2]);
        float s3 = sigmoidf(logits[k * 5 + 3]);
        float s4 = sigmoidf(logits[k * 5 + 4]);
        g_p4[k] = make_float4(s0, s1, s2, s3);
        g_c4[k] = s4;
    }
}

// ---- kernel B: fused broadcast-copy + recurrence resolve + probs + patch ----
__global__ __launch_bounds__(THREADS)
void fused_kernel(const int* __restrict__ prev_kc,
                  const int* __restrict__ curr_kc,
                  const int* __restrict__ prev_corr,
                  float* __restrict__ out)
{
    __shared__ int   sPK[TT];      // TT=100 = 25 int4
    __shared__ int   sPW[TT];
    __shared__ float sVal[TT];
    __shared__ int   sMaxD;

    const int b   = blockIdx.x;
    const int tid = threadIdx.x;

    float* __restrict__ orow = out + (size_t)BB * TT + (size_t)b * NKC;

    // ---- phase 0 (split warps): warps 4-7 bulk-copy, warps 0-3 gather ----
    int   pk = -1, ck = -1;
    float A = 0.f, Bc = 0.f, P0 = 0.f, E = 0.f, F = 0.f, G = 0.f;
    float initSkill = 0.f, initCs = 0.f;

    if (tid >= 128) {
        // bulk copy: default state row -> out (g_c4 is L2-resident, 512x reuse)
        const float4* __restrict__ src = (const float4*)g_c4;
        float4*       __restrict__ dst = (float4*)orow;
        #pragma unroll 2
        for (int i = tid - 128; i < NKC / 4; i += 128)
            dst[i] = src[i];
    } else {
        if (tid == 0) sMaxD = 0;
        if (tid < TT) {
            ck = curr_kc[b * TT + tid];
            pk = prev_kc[b * TT + tid];
            const int c = prev_corr[b * TT + tid];
            sPK[tid] = (tid >= 1) ? pk : -9;   // step 0 performs no update
            const float4 cp = g_p4[ck];
            G = cp.z;
            F = cp.w - cp.z;
            initCs = g_c4[ck];
            if (tid >= 1) {
                const float4 pp = g_p4[pk];
                A  = c ? pp.w : (1.0f - pp.w);    // p_out[:,1]
                Bc = c ? pp.z : (1.0f - pp.z);    // p_out[:,0]
                P0 = pp.x;
                E  = 1.0f - pp.y - pp.x;
                initSkill = g_c4[pk];
            }
        }
    }
    __syncthreads();

    // ---- dependency scan (int4 over 100 steps = 25 iterations) ----
    int  pw = -1;          // last s' <  tid writing pk  (skill source)
    int  w  = -1;          // last s' <= tid writing ck  (probs source)
    bool isLast = true;    // no s' > tid writes pk
    if (tid < TT) {
        const int4* sp4 = (const int4*)sPK;
        #pragma unroll 5
        for (int j = 0; j < TT / 4; j++) {
            const int4 v = *(sp4 + j);
            const int s0 = 4 * j;
            if (v.x == pk) { if (s0     < tid) pw = s0;     else if (s0     > tid) isLast = false; }
            if (v.y == pk) { if (s0 + 1 < tid) pw = s0 + 1; else if (s0 + 1 > tid) isLast = false; }
            if (v.z == pk) { if (s0 + 2 < tid) pw = s0 + 2; else if (s0 + 2 > tid) isLast = false; }
            if (v.w == pk) { if (s0 + 3 < tid) pw = s0 + 3; else if (s0 + 3 > tid) isLast = false; }
            if (v.x == ck && s0     <= tid) w = s0;
            if (v.y == ck && s0 + 1 <= tid) w = s0 + 1;
            if (v.z == ck && s0 + 2 <= tid) w = s0 + 2;
            if (v.w == ck && s0 + 3 <= tid) w = s0 + 3;
        }
        sPW[tid] = pw;
    }
    __syncthreads();

    // ---- chain depth via pointer chase (depth ~1-4) ----
    int depth = 0;
    if (tid >= 1 && tid < TT) {
        int j = pw;
        while (j >= 0) { j = sPW[j]; depth++; }
        atomicMax(&sMaxD, depth);
    }
    __syncthreads();
    const int maxD = sMaxD;

    // ---- wavefront by depth: one uniform barrier per round ----
    float myVal = 0.f;
    for (int r = 0; r <= maxD; r++) {
        if (tid >= 1 && tid < TT && depth == r) {
            const float skill = (r == 0) ? initSkill : sVal[pw];
            const float num   = A * skill;
            const float den   = fmaf(Bc, -skill, Bc) + num;   // B*(1-skill)+A*skill
            const float filt  = __fdividef(num, den);
            myVal = fmaf(E, filt, P0);
            sVal[tid] = myVal;
        }
        __syncthreads();
    }

    // ---- probs + sparse patch (barriers above order patch after copy) ----
    if (tid < TT) {
        const float cs = (w < 0) ? initCs : sVal[w];
        out[b * TT + tid] = fmaf(F, cs, G);
        if (tid >= 1 && isLast)
            orow[pk] = myVal;
    }
}

extern "C" void kernel_launch(void* const* d_in, const int* in_sizes, int n_in,
                              void* d_out, int out_size) {
    const int*   prev_kc   = (const int*)d_in[0];
    const int*   curr_kc   = (const int*)d_in[1];
    const int*   prev_corr = (const int*)d_in[2];
    const float* kc_logits = (const float*)d_in[3];
    float*       out       = (float*)d_out;

    tbl_kernel  <<<(NKC + 127) / 128, 128>>>(kc_logits);
    fused_kernel<<<BB, THREADS>>>(prev_kc, curr_kc, prev_corr, out);
}

// round 7
// speedup vs baseline: 1.3200x; 1.1750x over previous
#include <cuda_runtime.h>
#include <cuda_bf16.h>

#define NKC 5000
#define BB  512
#define TT  100
#define THREADS 256
#define TBL_SLICE 10   // table entries built per block (512*10 >= 5000)

__device__ float  g_c4[NKC];   // sigmoid(logits[:,4]) — initial/default state
__device__ float4 g_p4[NKC];   // sigmoid(logits[:,0..3])
__device__ int    g_ready;     // blocks that published their table slice
__device__ int    g_done;      // blocks fully finished (for counter reset)

__device__ __forceinline__ float sigmoidf(float x) {
    return 1.0f / (1.0f + __expf(-x));
}

__global__ __launch_bounds__(THREADS)
void fused_kernel(const int* __restrict__ prev_kc,
                  const int* __restrict__ curr_kc,
                  const int* __restrict__ prev_corr,
                  const float* __restrict__ logits,
                  float* __restrict__ out)
{
    __shared__ int   sPK[TT];
    __shared__ int   sPW[TT];
    __shared__ float sVal[TT];
    __shared__ int   sMaxD;

    const int b   = blockIdx.x;
    const int tid = threadIdx.x;

    float* __restrict__ orow = out + (size_t)BB * TT + (size_t)b * NKC;

    // ---- phase 0: index loads (table-independent) + table-slice build ----
    int pk = -1, ck = -1, c = 0;
    if (tid == 0) sMaxD = 0;
    if (tid < TT) {
        ck = curr_kc[b * TT + tid];
        pk = prev_kc[b * TT + tid];
        c  = prev_corr[b * TT + tid];
        sPK[tid] = (tid >= 1) ? pk : -9;     // step 0 performs no update
    } else if (tid >= 128 && tid < 128 + TBL_SLICE) {
        const int k = b * TBL_SLICE + (tid - 128);
        if (k < NKC) {
            const float s0 = sigmoidf(logits[k * 5 + 0]);
            const float s1 = sigmoidf(logits[k * 5 + 1]);
            const float s2 = sigmoidf(logits[k * 5 + 2]);
            const float s3 = sigmoidf(logits[k * 5 + 3]);
            const float s4 = sigmoidf(logits[k * 5 + 4]);
            g_p4[k] = make_float4(s0, s1, s2, s3);
            g_c4[k] = s4;
        }
    }
    __syncthreads();                          // table-slice stores ordered before arrive
    if (tid == 0) {
        __threadfence();
        atomicAdd(&g_ready, 1);
    }

    // ---- dependency scan (table-independent; overlaps other blocks' builds) ----
    int  pw = -1;          // last s' <  tid writing pk  (skill source)
    int  w  = -1;          // last s' <= tid writing ck  (probs source)
    bool isLast = true;    // no s' > tid writes pk
    if (tid < TT) {
        const int4* sp4 = (const int4*)sPK;
        #pragma unroll 5
        for (int j = 0; j < TT / 4; j++) {
            const int4 v = *(sp4 + j);
            const int s0 = 4 * j;
            if (v.x == pk) { if (s0     < tid) pw = s0;     else if (s0     > tid) isLast = false; }
            if (v.y == pk) { if (s0 + 1 < tid) pw = s0 + 1; else if (s0 + 1 > tid) isLast = false; }
            if (v.z == pk) { if (s0 + 2 < tid) pw = s0 + 2; else if (s0 + 2 > tid) isLast = false; }
            if (v.w == pk) { if (s0 + 3 < tid) pw = s0 + 3; else if (s0 + 3 > tid) isLast = false; }
            if (v.x == ck && s0     <= tid) w = s0;
            if (v.y == ck && s0 + 1 <= tid) w = s0 + 1;
            if (v.z == ck && s0 + 2 <= tid) w = s0 + 2;
            if (v.w == ck && s0 + 3 <= tid) w = s0 + 3;
        }
        sPW[tid] = pw;
    }
    __syncthreads();

    // ---- chain depth via pointer chase (depth ~1-4) ----
    int depth = 0;
    if (tid >= 1 && tid < TT) {
        int j = pw;
        while (j >= 0) { j = sPW[j]; depth++; }
        atomicMax(&sMaxD, depth);
    }

    // ---- grid handshake: wait for all 512 table slices ----
    if (tid == 0) {
        while (*(volatile int*)&g_ready < BB)
            __nanosleep(40);
        __threadfence();
    }
    __syncthreads();                          // publishes sMaxD too
    const int maxD = sMaxD;

    // ---- table-dependent phase: constants gather + bulk copy ----
    float A = 0.f, Bc = 0.f, P0 = 0.f, E = 0.f, F = 0.f, G = 0.f;
    float initSkill = 0.f, initCs = 0.f;
    if (tid < TT) {
        const float4 cp = g_p4[ck];
        G = cp.z;
        F = cp.w - cp.z;
        initCs = g_c4[ck];
        if (tid >= 1) {
            const float4 pp = g_p4[pk];
            A  = c ? pp.w : (1.0f - pp.w);    // p_out[:,1]
            Bc = c ? pp.z : (1.0f - pp.z);    // p_out[:,0]
            P0 = pp.x;
            E  = 1.0f - pp.y - pp.x;
            initSkill = g_c4[pk];
        }
    } else if (tid >= 128) {
        // bulk copy: default state row -> out (g_c4 is L2-resident, 512x reuse)
        const float4* __restrict__ src = (const float4*)g_c4;
        float4*       __restrict__ dst = (float4*)orow;
        #pragma unroll 2
        for (int i = tid - 128; i < NKC / 4; i += 128)
            dst[i] = src[i];
    }

    // ---- wavefront by depth: one uniform barrier per round ----
    float myVal = 0.f;
    for (int r = 0; r <= maxD; r++) {
        __syncthreads();
        if (tid >= 1 && tid < TT && depth == r) {
            const float skill = (r == 0) ? initSkill : sVal[pw];
            const float num   = A * skill;
            const float den   = fmaf(Bc, -skill, Bc) + num;   // B*(1-skill)+A*skill
            const float filt  = __fdividef(num, den);
            myVal = fmaf(E, filt, P0);
            sVal[tid] = myVal;
        }
    }
    __syncthreads();

    // ---- probs + sparse patch (barrier orders patch after bulk copy) ----
    if (tid < TT) {
        const float cs = (w < 0) ? initCs : sVal[w];
        out[b * TT + tid] = fmaf(F, cs, G);
        if (tid >= 1 && isLast)
            orow[pk] = myVal;
    }

    // ---- counter reset for next graph replay ----
    __syncthreads();
    if (tid == 0) {
        const int d = atomicAdd(&g_done, 1);
        if (d == BB - 1) {          // last block: everyone has passed the spin
            g_ready = 0;
            g_done  = 0;
        }
    }
}

extern "C" void kernel_launch(void* const* d_in, const int* in_sizes, int n_in,
                              void* d_out, int out_size) {
    const int*   prev_kc   = (const int*)d_in[0];
    const int*   curr_kc   = (const int*)d_in[1];
    const int*   prev_corr = (const int*)d_in[2];
    const float* kc_logits = (const float*)d_in[3];
    float*       out       = (float*)d_out;

    fused_kernel<<<BB, THREADS>>>(prev_kc, curr_kc, prev_corr, kc_logits, out);
}

// round 8
// speedup vs baseline: 1.3233x; 1.0025x over previous
#include <cuda_runtime.h>
#include <cuda_bf16.h>

#define NKC 5000
#define BB  512
#define TT  100
#define THREADS 256
#define TBL_SLICE 10   // table entries built per block (512*10 >= 5000)

__device__ float  g_c4[NKC];   // sigmoid(logits[:,4]) — initial/default state
__device__ float4 g_p4[NKC];   // sigmoid(logits[:,0..3])
__device__ int    g_ready;     // blocks that published their table slice
__device__ int    g_done;      // blocks fully finished (for counter reset)

__device__ __forceinline__ float sigmoidf(float x) {
    return 1.0f / (1.0f + __expf(-x));
}

__global__ __launch_bounds__(THREADS)
void fused_kernel(const int* __restrict__ prev_kc,
                  const int* __restrict__ curr_kc,
                  const int* __restrict__ prev_corr,
                  const float* __restrict__ logits,
                  float* __restrict__ out)
{
    __shared__ int   sPK[TT];
    __shared__ int   sPW[TT];
    __shared__ float sVal[TT];
    __shared__ int   sNotLast[TT];
    __shared__ int   sMaxD;

    const int b   = blockIdx.x;
    const int tid = threadIdx.x;

    float* __restrict__ orow = out + (size_t)BB * TT + (size_t)b * NKC;

    // ---- phase 0a: warp 4 builds table slice FIRST and arrives (no block barrier) ----
    if (tid >= 128 && tid < 128 + TBL_SLICE) {
        const int k = b * TBL_SLICE + (tid - 128);
        if (k < NKC) {
            const float s0 = sigmoidf(logits[k * 5 + 0]);
            const float s1 = sigmoidf(logits[k * 5 + 1]);
            const float s2 = sigmoidf(logits[k * 5 + 2]);
            const float s3 = sigmoidf(logits[k * 5 + 3]);
            const float s4 = sigmoidf(logits[k * 5 + 4]);
            g_p4[k] = make_float4(s0, s1, s2, s3);
            g_c4[k] = s4;
        }
        __threadfence();                       // publish this lane's stores
        __syncwarp(0x3FF);                     // lanes 0-9 of warp 4
        if (tid == 128)
            atomicAdd(&g_ready, 1);
    }

    // ---- phase 0b: index loads (table-independent) ----
    int pk = -1, ck = -1, c = 0;
    if (tid == 0) sMaxD = 0;
    if (tid < TT) {
        ck = curr_kc[b * TT + tid];
        pk = prev_kc[b * TT + tid];
        c  = prev_corr[b * TT + tid];
        sPK[tid]      = (tid >= 1) ? pk : -9;  // step 0 performs no update
        sNotLast[tid] = 0;
    }
    __syncthreads();

    // ---- predecessor-only dependency scan (avg 12.5 int4 iters) ----
    int pw = -1;           // last s' <  tid writing pk  (skill source)
    int w  = -1;           // last s' <= tid writing ck  (probs source)
    if (tid < TT) {
        const int4* sp4 = (const int4*)sPK;
        const int jmax = tid >> 2;             // elements beyond tid can't qualify
        for (int j = 0; j <= jmax; j++) {
            const int4 v = sp4[j];
            const int s0 = 4 * j;
            if (v.x == pk && s0     < tid) pw = s0;
            if (v.y == pk && s0 + 1 < tid) pw = s0 + 1;
            if (v.z == pk && s0 + 2 < tid) pw = s0 + 2;
            if (v.w == pk && s0 + 3 < tid) pw = s0 + 3;
            if (v.x == ck && s0     <= tid) w = s0;
            if (v.y == ck && s0 + 1 <= tid) w = s0 + 1;
            if (v.z == ck && s0 + 2 <= tid) w = s0 + 2;
            if (v.w == ck && s0 + 3 <= tid) w = s0 + 3;
        }
        sPW[tid] = pw;
        if (pw >= 0) sNotLast[pw] = 1;         // pw values are distinct -> plain store
    }
    __syncthreads();

    // ---- chain depth via pointer chase (depth ~1-4) ----
    int depth = 0;
    if (tid >= 1 && tid < TT) {
        int j = pw;
        while (j >= 0) { j = sPW[j]; depth++; }
        atomicMax(&sMaxD, depth);
    }

    // ---- grid handshake: wait for all 512 table slices ----
    if (tid == 0) {
        while (*(volatile int*)&g_ready < BB)
            __nanosleep(20);
        __threadfence();
    }
    __syncthreads();                           // publishes sMaxD too
    const int maxD = sMaxD;

    // ---- table-dependent: constants gather (warps 0-3) + bulk copy (warps 4-7) ----
    float A = 0.f, Bc = 0.f, P0 = 0.f, E = 0.f, F = 0.f, G = 0.f;
    float initSkill = 0.f, initCs = 0.f;
    if (tid < TT) {
        const float4 cp = g_p4[ck];
        G = cp.z;
        F = cp.w - cp.z;
        initCs = g_c4[ck];
        if (tid >= 1) {
            const float4 pp = g_p4[pk];
            A  = c ? pp.w : (1.0f - pp.w);     // p_out[:,1]
            Bc = c ? pp.z : (1.0f - pp.z);     // p_out[:,0]
            P0 = pp.x;
            E  = 1.0f - pp.y - pp.x;
            initSkill = g_c4[pk];
        }
    } else if (tid >= 128) {
        // bulk copy with MLP=10: all loads issued before any store
        const float4* __restrict__ src = (const float4*)g_c4;
        float4*       __restrict__ dst = (float4*)orow;
        const int base = tid - 128;
        float4 v[10];
        #pragma unroll
        for (int u = 0; u < 10; u++) {
            const int i = base + u * 128;
            if (i < NKC / 4) v[u] = src[i];
        }
        #pragma unroll
        for (int u = 0; u < 10; u++) {
            const int i = base + u * 128;
            if (i < NKC / 4) dst[i] = v[u];
        }
    }

    // ---- wavefront by depth: one uniform barrier per round ----
    float myVal = 0.f;
    for (int r = 0; r <= maxD; r++) {
        __syncthreads();
        if (tid >= 1 && tid < TT && depth == r) {
            const float skill = (r == 0) ? initSkill : sVal[pw];
            const float num   = A * skill;
            const float den   = fmaf(Bc, -skill, Bc) + num;   // B*(1-skill)+A*skill
            const float filt  = __fdividef(num, den);
            myVal = fmaf(E, filt, P0);
            sVal[tid] = myVal;
        }
    }
    __syncthreads();

    // ---- probs + sparse patch (barrier orders patch after bulk copy) ----
    if (tid < TT) {
        const float cs = (w < 0) ? initCs : sVal[w];
        out[b * TT + tid] = fmaf(F, cs, G);
        if (tid >= 1 && !sNotLast[tid])
            orow[pk] = myVal;
    }

    // ---- counter reset for next graph replay ----
    __syncthreads();
    if (tid == 0) {
        const int d = atomicAdd(&g_done, 1);
        if (d == BB - 1) {           // last block: everyone has passed the spin
            g_ready = 0;
            g_done  = 0;
        }
    }
}

extern "C" void kernel_launch(void* const* d_in, const int* in_sizes, int n_in,
                              void* d_out, int out_size) {
    const int*   prev_kc   = (const int*)d_in[0];
    const int*   curr_kc   = (const int*)d_in[1];
    const int*   prev_corr = (const int*)d_in[2];
    const float* kc_logits = (const float*)d_in[3];
    float*       out       = (float*)d_out;

    fused_kernel<<<BB, THREADS>>>(prev_kc, curr_kc, prev_corr, kc_logits, out);
}